// round 1
// baseline (speedup 1.0000x reference)
#include <cuda_runtime.h>
#include <math.h>

// Problem constants
#define B_  64
#define T_  32
#define S_  33            // T+1
#define V_  32000
#define E_  512
#define H_  1024
#define G4  4096          // 4*H
#define M1  (S_*B_)       // 2112 rows of the input-projection GEMM

#define KSPLIT 2

// GEMM tiling
#define BM 64
#define BN 64
#define BK 16
#define NTHREADS 128

// Scratch (static __device__ arrays; no allocations allowed)
__device__ float g_x   [M1 * E_];          // gathered inputs  [2112, 512]
__device__ float g_xg  [M1 * G4];          // x @ w_ih^T       [2112, 4096]
__device__ float g_h   [B_ * H_];
__device__ float g_c   [B_ * H_];
__device__ float g_part[KSPLIT * B_ * G4]; // k-split partials of h @ w_hh^T

// ---------------------------------------------------------------------------
// Packed f32x2 helpers (FFMA2 path — ptxas never emits this from C++)
// ---------------------------------------------------------------------------
__device__ __forceinline__ void ffma2(unsigned long long& d,
                                      unsigned long long a,
                                      unsigned long long b) {
    asm("fma.rn.f32x2 %0, %1, %2, %0;" : "+l"(d) : "l"(a), "l"(b));
}
__device__ __forceinline__ unsigned long long splat2(float x) {
    unsigned long long r;
    asm("mov.b64 %0, {%1, %1};" : "=l"(r) : "f"(x));
    return r;
}

// ---------------------------------------------------------------------------
// 1) Build inputs: row m = t*64+b ; t==0 -> features, else W_embed gather
// ---------------------------------------------------------------------------
__global__ void build_x_kernel(const float* __restrict__ features,
                               const int*   __restrict__ captions,
                               const float* __restrict__ W_embed,
                               const float* __restrict__ b_embed) {
    int idx = blockIdx.x * blockDim.x + threadIdx.x;
    if (idx >= M1 * E_) return;
    int m = idx >> 9;          // / 512
    int e = idx & 511;
    int t = m >> 6;
    int b = m & 63;
    float v;
    if (t == 0) {
        v = features[b * E_ + e];
    } else {
        int cap = captions[b * T_ + (t - 1)];
        v = W_embed[e * V_ + cap] + b_embed[e];
    }
    g_x[idx] = v;
}

// ---------------------------------------------------------------------------
// 2) Generic NT GEMM:  C[m,n] (+)= sum_k A[m,k]*Bm[n,k]  over k in [z*kLen, (z+1)*kLen)
//    blockIdx.x -> n tile, blockIdx.y -> m tile, blockIdx.z -> k slice
//    Thread tile 8m x 4n, FFMA2 packed along m.
// ---------------------------------------------------------------------------
__global__ __launch_bounds__(NTHREADS)
void gemm_nt_kernel(const float* __restrict__ A, int lda,
                    const float* __restrict__ Bm, int ldb,
                    float* __restrict__ C, int ldc, int zStride,
                    int kLen) {
    __shared__ float As[BK][BM];
    __shared__ float Bs[BK][BN];

    const int tid = threadIdx.x;
    const int m0 = blockIdx.y * BM;
    const int n0 = blockIdx.x * BN;
    const int kStart = blockIdx.z * kLen;
    C += (size_t)blockIdx.z * zStride;

    const int nx = tid & 15;   // 0..15 -> 4 n each
    const int my = tid >> 4;   // 0..7  -> 8 m each

    // Global tile loads: 2 float4 per operand per thread
    const int r0 = tid >> 2;          // rows 0..31
    const int q0 = tid & 3;
    const int r1 = r0 + 32;           // rows 32..63 (since (tid+128)>>2)

    const float* Ag0 = A + (size_t)(m0 + r0) * lda + kStart + q0 * 4;
    const float* Ag1 = A + (size_t)(m0 + r1) * lda + kStart + q0 * 4;
    const float* Bg0 = Bm + (size_t)(n0 + r0) * ldb + kStart + q0 * 4;
    const float* Bg1 = Bm + (size_t)(n0 + r1) * ldb + kStart + q0 * 4;

    unsigned long long acc[4][4];
#pragma unroll
    for (int i = 0; i < 4; i++)
#pragma unroll
        for (int j = 0; j < 4; j++) acc[i][j] = 0ull;

    const int nk = kLen / BK;

    float4 pa0 = *(const float4*)(Ag0);
    float4 pa1 = *(const float4*)(Ag1);
    float4 pb0 = *(const float4*)(Bg0);
    float4 pb1 = *(const float4*)(Bg1);

    for (int kt = 0; kt < nk; kt++) {
        // commit current tile to smem (transposed: [k][m])
        As[q0 * 4 + 0][r0] = pa0.x; As[q0 * 4 + 1][r0] = pa0.y;
        As[q0 * 4 + 2][r0] = pa0.z; As[q0 * 4 + 3][r0] = pa0.w;
        As[q0 * 4 + 0][r1] = pa1.x; As[q0 * 4 + 1][r1] = pa1.y;
        As[q0 * 4 + 2][r1] = pa1.z; As[q0 * 4 + 3][r1] = pa1.w;
        Bs[q0 * 4 + 0][r0] = pb0.x; Bs[q0 * 4 + 1][r0] = pb0.y;
        Bs[q0 * 4 + 2][r0] = pb0.z; Bs[q0 * 4 + 3][r0] = pb0.w;
        Bs[q0 * 4 + 0][r1] = pb1.x; Bs[q0 * 4 + 1][r1] = pb1.y;
        Bs[q0 * 4 + 2][r1] = pb1.z; Bs[q0 * 4 + 3][r1] = pb1.w;
        __syncthreads();

        // prefetch next tile (overlap global latency with compute)
        if (kt + 1 < nk) {
            pa0 = *(const float4*)(Ag0 + (kt + 1) * BK);
            pa1 = *(const float4*)(Ag1 + (kt + 1) * BK);
            pb0 = *(const float4*)(Bg0 + (kt + 1) * BK);
            pb1 = *(const float4*)(Bg1 + (kt + 1) * BK);
        }

#pragma unroll
        for (int kk = 0; kk < BK; kk++) {
            // a: 8 m-values as 4 packed f32x2 (m pairs are adjacent in As)
            ulonglong2 aA = *(const ulonglong2*)(&As[kk][my * 8]);
            ulonglong2 aB = *(const ulonglong2*)(&As[kk][my * 8 + 4]);
            float4 b4 = *(const float4*)(&Bs[kk][nx * 4]);
            unsigned long long bb0 = splat2(b4.x);
            unsigned long long bb1 = splat2(b4.y);
            unsigned long long bb2 = splat2(b4.z);
            unsigned long long bb3 = splat2(b4.w);

            ffma2(acc[0][0], aA.x, bb0); ffma2(acc[0][1], aA.x, bb1);
            ffma2(acc[0][2], aA.x, bb2); ffma2(acc[0][3], aA.x, bb3);
            ffma2(acc[1][0], aA.y, bb0); ffma2(acc[1][1], aA.y, bb1);
            ffma2(acc[1][2], aA.y, bb2); ffma2(acc[1][3], aA.y, bb3);
            ffma2(acc[2][0], aB.x, bb0); ffma2(acc[2][1], aB.x, bb1);
            ffma2(acc[2][2], aB.x, bb2); ffma2(acc[2][3], aB.x, bb3);
            ffma2(acc[3][0], aB.y, bb0); ffma2(acc[3][1], aB.y, bb1);
            ffma2(acc[3][2], aB.y, bb2); ffma2(acc[3][3], aB.y, bb3);
        }
        __syncthreads();
    }

    // epilogue: acc[i][j] holds rows (my*8+2i, my*8+2i+1) of column nx*4+j
#pragma unroll
    for (int i = 0; i < 4; i++) {
        int m = m0 + my * 8 + i * 2;
#pragma unroll
        for (int j = 0; j < 4; j++) {
            int n = n0 + nx * 4 + j;
            float2 v = *reinterpret_cast<float2*>(&acc[i][j]);
            C[(size_t)m * ldc + n] = v.x;
            C[(size_t)(m + 1) * ldc + n] = v.y;
        }
    }
}

// ---------------------------------------------------------------------------
// 3) Combine: gates = xg + sum(partials) + b_ih + b_hh ; LSTM cell update.
// ---------------------------------------------------------------------------
__global__ void combine_kernel(int t,
                               const float* __restrict__ b_ih,
                               const float* __restrict__ b_hh,
                               float* __restrict__ out) {
    int idx = blockIdx.x * blockDim.x + threadIdx.x;
    if (idx >= B_ * H_) return;
    int b = idx >> 10;
    int j = idx & 1023;

    const float* xr = g_xg + (size_t)(t * B_ + b) * G4;
    const float* p0 = g_part + (size_t)b * G4;
    const float* p1 = g_part + (size_t)(B_ + b) * G4;

    float gi = xr[j]           + p0[j]           + p1[j]           + b_ih[j]           + b_hh[j];
    float gf = xr[H_ + j]      + p0[H_ + j]      + p1[H_ + j]      + b_ih[H_ + j]      + b_hh[H_ + j];
    float gg = xr[2 * H_ + j]  + p0[2 * H_ + j]  + p1[2 * H_ + j]  + b_ih[2 * H_ + j]  + b_hh[2 * H_ + j];
    float go = xr[3 * H_ + j]  + p0[3 * H_ + j]  + p1[3 * H_ + j]  + b_ih[3 * H_ + j]  + b_hh[3 * H_ + j];

    float ii = 1.0f / (1.0f + expf(-gi));
    float ff = 1.0f / (1.0f + expf(-gf));
    float gt = tanhf(gg);
    float oo = 1.0f / (1.0f + expf(-go));

    float c = ff * g_c[idx] + ii * gt;
    float h = oo * tanhf(c);

    g_c[idx] = c;
    g_h[idx] = h;
    out[((size_t)b * S_ + t) * H_ + j] = h;
}

// ---------------------------------------------------------------------------
// Launcher (graph-capturable: kernels + async D2D copies only)
// ---------------------------------------------------------------------------
extern "C" void kernel_launch(void* const* d_in, const int* in_sizes, int n_in,
                              void* d_out, int out_size) {
    const float* features = (const float*)d_in[0];
    const int*   captions = (const int*)  d_in[1];
    const float* W_embed  = (const float*)d_in[2];
    const float* b_embed  = (const float*)d_in[3];
    const float* w_ih     = (const float*)d_in[4];
    const float* w_hh     = (const float*)d_in[5];
    const float* b_ih     = (const float*)d_in[6];
    const float* b_hh     = (const float*)d_in[7];
    const float* h0       = (const float*)d_in[8];
    const float* c0       = (const float*)d_in[9];
    float* out = (float*)d_out;

    float *px, *pxg, *ph, *pc, *ppart;
    cudaGetSymbolAddress((void**)&px,    g_x);
    cudaGetSymbolAddress((void**)&pxg,   g_xg);
    cudaGetSymbolAddress((void**)&ph,    g_h);
    cudaGetSymbolAddress((void**)&pc,    g_c);
    cudaGetSymbolAddress((void**)&ppart, g_part);

    // Inputs gather (one-hot @ Linear == column gather of W_embed)
    build_x_kernel<<<(M1 * E_ + 255) / 256, 256>>>(features, captions, W_embed, b_embed);

    // Time-parallel input projection: g_xg = g_x @ w_ih^T  (M=2112, N=4096, K=512)
    gemm_nt_kernel<<<dim3(G4 / BN, M1 / BM, 1), NTHREADS>>>(
        px, E_, w_ih, E_, pxg, G4, 0, E_);

    // Init recurrent state
    cudaMemcpyAsync(ph, h0, B_ * H_ * sizeof(float), cudaMemcpyDeviceToDevice, 0);
    cudaMemcpyAsync(pc, c0, B_ * H_ * sizeof(float), cudaMemcpyDeviceToDevice, 0);

    // Sequential recurrence: 33 x (h @ w_hh^T split-K, then gate fuse)
    for (int t = 0; t < S_; t++) {
        gemm_nt_kernel<<<dim3(G4 / BN, 1, KSPLIT), NTHREADS>>>(
            ph, H_, w_hh, H_, ppart, G4, B_ * G4, H_ / KSPLIT);
        combine_kernel<<<(B_ * H_ + 255) / 256, 256>>>(t, b_ih, b_hh, out);
    }
}